// round 1
// baseline (speedup 1.0000x reference)
#include <cuda_runtime.h>
#include <cuda_bf16.h>
#include <cstdint>

// Problem constants
#define BATCH 4096
#define NDIM  64            // N == D == 64
#define FDIM  4096
#define KP    2080          // N*(N+1)/2
#define EMB_ELEMS (4096u*4096u)   // B * N*D  == B * F

// Scratch: gathered triu/tril matrices, fp32, (B x KP)
__device__ float g_triu[(size_t)BATCH * KP];
__device__ float g_tril[(size_t)BATCH * KP];

// ---------------------------------------------------------------------------
// Kernel A: per-batch embs_kp = F @ kpW @ F^T  (64x64), scatter into triu/tril
// One block per batch. 256 threads as 16x16, each owns a 4x4 tile.
// Shared: Fs padded to 65 floats/row (kills the column-read bank conflict in
// GEMM2), WT holds kp_W during GEMM1 then is reused to hold T = F@kpW.
// ---------------------------------------------------------------------------
__global__ __launch_bounds__(256) void kp_pair_kernel(
    const float* __restrict__ femb, const float* __restrict__ kpW)
{
    __shared__ float Fs[64 * 65];
    __shared__ float WT[64 * 64];

    const int b   = blockIdx.x;
    const int tid = threadIdx.x;
    const float* Fb = femb + (size_t)b * (NDIM * NDIM);

    // Load F (padded rows) and kp_W
    for (int i = tid; i < 1024; i += 256) {           // 1024 float4 = 4096 floats
        float4 v = ((const float4*)Fb)[i];
        int row = i >> 4, col = (i & 15) << 2;
        float* dst = &Fs[row * 65 + col];
        dst[0] = v.x; dst[1] = v.y; dst[2] = v.z; dst[3] = v.w;
    }
    for (int i = tid; i < 1024; i += 256) {
        ((float4*)WT)[i] = ((const float4*)kpW)[i];
    }
    __syncthreads();

    const int ty = tid >> 4, tx = tid & 15;
    const int r0 = ty * 4, c0 = tx * 4;

    // GEMM1: T[n,e] = sum_d F[n,d] * W[d,e]   (accumulate in registers)
    float t[4][4] = {};
    #pragma unroll 8
    for (int d = 0; d < 64; d++) {
        float a0 = Fs[(r0 + 0) * 65 + d];
        float a1 = Fs[(r0 + 1) * 65 + d];
        float a2 = Fs[(r0 + 2) * 65 + d];
        float a3 = Fs[(r0 + 3) * 65 + d];
        float4 bb = *(const float4*)&WT[d * 64 + c0];
        t[0][0] += a0 * bb.x; t[0][1] += a0 * bb.y; t[0][2] += a0 * bb.z; t[0][3] += a0 * bb.w;
        t[1][0] += a1 * bb.x; t[1][1] += a1 * bb.y; t[1][2] += a1 * bb.z; t[1][3] += a1 * bb.w;
        t[2][0] += a2 * bb.x; t[2][1] += a2 * bb.y; t[2][2] += a2 * bb.z; t[2][3] += a2 * bb.w;
        t[3][0] += a3 * bb.x; t[3][1] += a3 * bb.y; t[3][2] += a3 * bb.z; t[3][3] += a3 * bb.w;
    }
    __syncthreads();   // everyone done reading kp_W from WT

    // Store T into WT (reuse)
    #pragma unroll
    for (int i = 0; i < 4; i++) {
        float4 v = make_float4(t[i][0], t[i][1], t[i][2], t[i][3]);
        *(float4*)&WT[(r0 + i) * 64 + c0] = v;
    }
    __syncthreads();

    // GEMM2: E[n,m] = sum_e T[n,e] * F[m,e]
    float e[4][4] = {};
    #pragma unroll 8
    for (int d = 0; d < 64; d++) {
        float a0 = WT[(r0 + 0) * 64 + d];
        float a1 = WT[(r0 + 1) * 64 + d];
        float a2 = WT[(r0 + 2) * 64 + d];
        float a3 = WT[(r0 + 3) * 64 + d];
        float b0 = Fs[(c0 + 0) * 65 + d];
        float b1 = Fs[(c0 + 1) * 65 + d];
        float b2 = Fs[(c0 + 2) * 65 + d];
        float b3 = Fs[(c0 + 3) * 65 + d];
        e[0][0] += a0 * b0; e[0][1] += a0 * b1; e[0][2] += a0 * b2; e[0][3] += a0 * b3;
        e[1][0] += a1 * b0; e[1][1] += a1 * b1; e[1][2] += a1 * b2; e[1][3] += a1 * b3;
        e[2][0] += a2 * b0; e[2][1] += a2 * b1; e[2][2] += a2 * b2; e[2][3] += a2 * b3;
        e[3][0] += a3 * b0; e[3][1] += a3 * b1; e[3][2] += a3 * b2; e[3][3] += a3 * b3;
    }

    // Scatter into triu/tril gathers.
    // triu (r<=c): p = r*64 - r*(r-1)/2 + (c-r)
    // tril (r>=c): p = r*(r+1)/2 + c
    float* triu_b = g_triu + (size_t)b * KP;
    float* tril_b = g_tril + (size_t)b * KP;
    #pragma unroll
    for (int i = 0; i < 4; i++) {
        int r = r0 + i;
        int tri_base = r * 64 - (r * (r - 1)) / 2 - r;  // + c later
        int trl_base = (r * (r + 1)) / 2;
        #pragma unroll
        for (int j = 0; j < 4; j++) {
            int c = c0 + j;
            float v = e[i][j];
            if (r <= c) triu_b[tri_base + c] = v;
            if (r >= c) tril_b[trl_base + c] = v;
        }
    }
}

// ---------------------------------------------------------------------------
// Kernel B: view = Gathered(B x KP) @ W^T (F x KP)  ->  (B x F)
// Classic 128x128x16 SGEMM, 256 threads, 8x8 per-thread microtile.
// blockIdx.z selects {triu, W_triu, out seg1} vs {tril, W_tril, out seg2}.
// M = 4096, N = 4096, K = 2080 (130 tiles of 16, exact).
// ---------------------------------------------------------------------------
__global__ __launch_bounds__(256) void view_gemm_kernel(
    const float* __restrict__ W_triu, const float* __restrict__ W_tril,
    float* __restrict__ out)
{
    constexpr int BM = 128, BN = 128, BK = 16;
    __shared__ float As[BK * BM];   // As[k][m]
    __shared__ float Bs[BK * BN];   // Bs[k][n]

    const float* A = (blockIdx.z == 0) ? g_triu : g_tril;
    const float* W = (blockIdx.z == 0) ? W_triu : W_tril;
    float* C = out + (size_t)(1 + blockIdx.z) * EMB_ELEMS;

    const int tid = threadIdx.x;
    const int m0 = blockIdx.y * BM;
    const int n0 = blockIdx.x * BN;

    const int lr = tid >> 2;            // 0..63
    const int lc = (tid & 3) << 2;      // 0,4,8,12
    const int ty = tid >> 4, tx = tid & 15;

    const float* Aptr  = A + (size_t)(m0 + lr) * KP + lc;
    const float* Aptr2 = Aptr + (size_t)64 * KP;
    const float* Wptr  = W + (size_t)(n0 + lr) * KP + lc;
    const float* Wptr2 = Wptr + (size_t)64 * KP;

    float acc[8][8] = {};

    for (int kt = 0; kt < KP; kt += BK) {
        float4 a0 = *(const float4*)(Aptr  + kt);
        float4 a1 = *(const float4*)(Aptr2 + kt);
        float4 b0 = *(const float4*)(Wptr  + kt);
        float4 b1 = *(const float4*)(Wptr2 + kt);

        __syncthreads();   // previous tile's compute finished
        As[(lc + 0) * BM + lr]      = a0.x;
        As[(lc + 1) * BM + lr]      = a0.y;
        As[(lc + 2) * BM + lr]      = a0.z;
        As[(lc + 3) * BM + lr]      = a0.w;
        As[(lc + 0) * BM + lr + 64] = a1.x;
        As[(lc + 1) * BM + lr + 64] = a1.y;
        As[(lc + 2) * BM + lr + 64] = a1.z;
        As[(lc + 3) * BM + lr + 64] = a1.w;
        Bs[(lc + 0) * BN + lr]      = b0.x;
        Bs[(lc + 1) * BN + lr]      = b0.y;
        Bs[(lc + 2) * BN + lr]      = b0.z;
        Bs[(lc + 3) * BN + lr]      = b0.w;
        Bs[(lc + 0) * BN + lr + 64] = b1.x;
        Bs[(lc + 1) * BN + lr + 64] = b1.y;
        Bs[(lc + 2) * BN + lr + 64] = b1.z;
        Bs[(lc + 3) * BN + lr + 64] = b1.w;
        __syncthreads();

        #pragma unroll
        for (int k = 0; k < BK; k++) {
            float ar[8], br[8];
            *(float4*)&ar[0] = *(const float4*)&As[k * BM + ty * 8];
            *(float4*)&ar[4] = *(const float4*)&As[k * BM + ty * 8 + 4];
            *(float4*)&br[0] = *(const float4*)&Bs[k * BN + tx * 8];
            *(float4*)&br[4] = *(const float4*)&Bs[k * BN + tx * 8 + 4];
            #pragma unroll
            for (int i = 0; i < 8; i++)
                #pragma unroll
                for (int j = 0; j < 8; j++)
                    acc[i][j] += ar[i] * br[j];
        }
    }

    // Epilogue: float4 stores
    #pragma unroll
    for (int i = 0; i < 8; i++) {
        size_t row = (size_t)(m0 + ty * 8 + i);
        float4 v0 = make_float4(acc[i][0], acc[i][1], acc[i][2], acc[i][3]);
        float4 v1 = make_float4(acc[i][4], acc[i][5], acc[i][6], acc[i][7]);
        *(float4*)&C[row * FDIM + n0 + tx * 8]     = v0;
        *(float4*)&C[row * FDIM + n0 + tx * 8 + 4] = v1;
    }
}

// ---------------------------------------------------------------------------
// Launch
// Inputs (metadata order): feature_emb (B*N*D f32), kp_W (D*D f32),
//                          W_triu (F*KP f32), W_tril (F*KP f32)
// Output: [embs_flatten | view_1 | view_2], each 4096*4096 f32.
// ---------------------------------------------------------------------------
extern "C" void kernel_launch(void* const* d_in, const int* in_sizes, int n_in,
                              void* d_out, int out_size)
{
    const float* femb   = (const float*)d_in[0];
    const float* kpW    = (const float*)d_in[1];
    const float* W_triu = (const float*)d_in[2];
    const float* W_tril = (const float*)d_in[3];
    float* out = (float*)d_out;

    // Segment 0: embs_flatten is just feature_emb flattened
    cudaMemcpyAsync(out, femb, (size_t)EMB_ELEMS * sizeof(float),
                    cudaMemcpyDeviceToDevice, 0);

    // Segment scratch: per-batch kernel product + triu/tril gather
    kp_pair_kernel<<<BATCH, 256>>>(femb, kpW);

    // Segments 1,2: the two big GEMMs
    dim3 grid(FDIM / 128, BATCH / 128, 2);
    view_gemm_kernel<<<grid, 256>>>(W_triu, W_tril, out);
}

// round 3
// speedup vs baseline: 2.6568x; 2.6568x over previous
#include <cuda_runtime.h>
#include <cuda_bf16.h>
#include <cstdint>

// ---------------------------------------------------------------------------
// Problem constants
// ---------------------------------------------------------------------------
#define BATCH 4096
#define NDIM  64
#define FDIM  4096
#define KP    2080          // N*(N+1)/2
#define KPAD  2112          // KP padded to a multiple of 32 (66 chunks of 32)
#define KW    (2*KPAD)      // row width of hi|lo planes (4224 bf16)
#define EMB_ELEMS (4096u*4096u)
#define NCHUNK (KPAD/32)    // 66

// bf16 hi/lo planes. Rows [0,4096) = view0 (triu / W_triu), [4096,8192) = view1.
// Cols [0,KPAD) = hi, [KPAD,2*KPAD) = lo. Pad cols [2080,2112) stay zero
// (device globals are zero-initialized and never written there).
__device__ __align__(1024) __nv_bfloat16 g_A [(size_t)8192 * KW];
__device__ __align__(1024) __nv_bfloat16 g_Wc[(size_t)8192 * KW];

// ---------------------------------------------------------------------------
// Small helpers
// ---------------------------------------------------------------------------
__device__ __forceinline__ uint32_t smem_to_u32(const void* p) {
    uint32_t a;
    asm("{ .reg .u64 t; cvta.to.shared.u64 t, %1; cvt.u32.u64 %0, t; }"
        : "=r"(a) : "l"(p));
    return a;
}

__device__ __forceinline__ void cp16(uint32_t dst, const void* src) {
    asm volatile("cp.async.cg.shared.global [%0], [%1], 16;"
                 :: "r"(dst), "l"(src));
}
#define CP_COMMIT() asm volatile("cp.async.commit_group;" ::: "memory")
#define CP_WAIT2()  asm volatile("cp.async.wait_group 2;" ::: "memory")

__device__ __forceinline__ void ldsm4(uint32_t (&r)[4], uint32_t addr) {
    asm volatile("ldmatrix.sync.aligned.m8n8.x4.shared.b16 {%0,%1,%2,%3}, [%4];"
                 : "=r"(r[0]), "=r"(r[1]), "=r"(r[2]), "=r"(r[3]) : "r"(addr));
}

__device__ __forceinline__ void mma_bf16(float (&d)[4], const uint32_t (&a)[4],
                                         uint32_t b0, uint32_t b1) {
    asm volatile(
        "mma.sync.aligned.m16n8k16.row.col.f32.bf16.bf16.f32 "
        "{%0,%1,%2,%3}, {%4,%5,%6,%7}, {%8,%9}, {%0,%1,%2,%3};"
        : "+f"(d[0]), "+f"(d[1]), "+f"(d[2]), "+f"(d[3])
        : "r"(a[0]), "r"(a[1]), "r"(a[2]), "r"(a[3]), "r"(b0), "r"(b1));
}

// XOR swizzle: tile row r (0..127), 16B-chunk c (0..3) -> byte offset in an
// 8KB plane. Guarantees 8 distinct 16B banks-groups within every ldmatrix
// phase (rows r..r+7, fixed c) and within cp.async store waves.
__device__ __forceinline__ uint32_t swz(uint32_t r, uint32_t c) {
    return (r * 4u + (c ^ ((r >> 1) & 3u))) * 16u;
}

// ---------------------------------------------------------------------------
// Kernel A: per-batch embs_kp = F @ kpW @ F^T, scatter triu/tril as bf16 hi/lo
// ---------------------------------------------------------------------------
__device__ __forceinline__ void split_store(__nv_bfloat16* row, int p, float v) {
    __nv_bfloat16 h = __float2bfloat16(v);
    float lo = v - __bfloat162float(h);
    row[p]        = h;
    row[KPAD + p] = __float2bfloat16(lo);
}

__global__ __launch_bounds__(256) void kp_pair_kernel(
    const float* __restrict__ femb, const float* __restrict__ kpW)
{
    __shared__ float Fs[64 * 65];
    __shared__ float WT[64 * 64];

    const int b   = blockIdx.x;
    const int tid = threadIdx.x;
    const float* Fb = femb + (size_t)b * (NDIM * NDIM);

    for (int i = tid; i < 1024; i += 256) {
        float4 v = ((const float4*)Fb)[i];
        int row = i >> 4, col = (i & 15) << 2;
        float* dst = &Fs[row * 65 + col];
        dst[0] = v.x; dst[1] = v.y; dst[2] = v.z; dst[3] = v.w;
    }
    for (int i = tid; i < 1024; i += 256)
        ((float4*)WT)[i] = ((const float4*)kpW)[i];
    __syncthreads();

    const int ty = tid >> 4, tx = tid & 15;
    const int r0 = ty * 4, c0 = tx * 4;

    float t[4][4] = {};
    #pragma unroll 8
    for (int d = 0; d < 64; d++) {
        float a0 = Fs[(r0 + 0) * 65 + d];
        float a1 = Fs[(r0 + 1) * 65 + d];
        float a2 = Fs[(r0 + 2) * 65 + d];
        float a3 = Fs[(r0 + 3) * 65 + d];
        float4 bb = *(const float4*)&WT[d * 64 + c0];
        t[0][0] += a0 * bb.x; t[0][1] += a0 * bb.y; t[0][2] += a0 * bb.z; t[0][3] += a0 * bb.w;
        t[1][0] += a1 * bb.x; t[1][1] += a1 * bb.y; t[1][2] += a1 * bb.z; t[1][3] += a1 * bb.w;
        t[2][0] += a2 * bb.x; t[2][1] += a2 * bb.y; t[2][2] += a2 * bb.z; t[2][3] += a2 * bb.w;
        t[3][0] += a3 * bb.x; t[3][1] += a3 * bb.y; t[3][2] += a3 * bb.z; t[3][3] += a3 * bb.w;
    }
    __syncthreads();
    #pragma unroll
    for (int i = 0; i < 4; i++)
        *(float4*)&WT[(r0 + i) * 64 + c0] = make_float4(t[i][0], t[i][1], t[i][2], t[i][3]);
    __syncthreads();

    float e[4][4] = {};
    #pragma unroll 8
    for (int d = 0; d < 64; d++) {
        float a0 = WT[(r0 + 0) * 64 + d];
        float a1 = WT[(r0 + 1) * 64 + d];
        float a2 = WT[(r0 + 2) * 64 + d];
        float a3 = WT[(r0 + 3) * 64 + d];
        float b0 = Fs[(c0 + 0) * 65 + d];
        float b1 = Fs[(c0 + 1) * 65 + d];
        float b2 = Fs[(c0 + 2) * 65 + d];
        float b3 = Fs[(c0 + 3) * 65 + d];
        e[0][0] += a0 * b0; e[0][1] += a0 * b1; e[0][2] += a0 * b2; e[0][3] += a0 * b3;
        e[1][0] += a1 * b0; e[1][1] += a1 * b1; e[1][2] += a1 * b2; e[1][3] += a1 * b3;
        e[2][0] += a2 * b0; e[2][1] += a2 * b1; e[2][2] += a2 * b2; e[2][3] += a2 * b3;
        e[3][0] += a3 * b0; e[3][1] += a3 * b1; e[3][2] += a3 * b2; e[3][3] += a3 * b3;
    }

    __nv_bfloat16* tri_row = g_A + (size_t)b * KW;            // view 0
    __nv_bfloat16* trl_row = g_A + (size_t)(4096 + b) * KW;   // view 1
    #pragma unroll
    for (int i = 0; i < 4; i++) {
        int r = r0 + i;
        int tri_base = r * 64 - (r * (r - 1)) / 2 - r;
        int trl_base = (r * (r + 1)) / 2;
        #pragma unroll
        for (int j = 0; j < 4; j++) {
            int c = c0 + j;
            float v = e[i][j];
            if (r <= c) split_store(tri_row, tri_base + c, v);
            if (r >= c) split_store(trl_row, trl_base + c, v);
        }
    }
}

// ---------------------------------------------------------------------------
// Kernel W: convert W_triu/W_tril fp32 -> bf16 hi/lo planes in g_Wc
// ---------------------------------------------------------------------------
__global__ __launch_bounds__(256) void convert_w_kernel(
    const float* __restrict__ Wt, const float* __restrict__ Wl)
{
    const size_t total = (size_t)2 * 4096 * 520;   // float4 quads
    size_t idx = (size_t)blockIdx.x * blockDim.x + threadIdx.x;
    if (idx >= total) return;
    int v = (int)(idx / ((size_t)4096 * 520));
    size_t rem = idx - (size_t)v * 4096 * 520;
    int f = (int)(rem / 520), q = (int)(rem % 520);

    const float* W = v ? Wl : Wt;
    float4 x = reinterpret_cast<const float4*>(W + (size_t)f * KP)[q];

    __nv_bfloat16 h0 = __float2bfloat16(x.x), h1 = __float2bfloat16(x.y);
    __nv_bfloat16 h2 = __float2bfloat16(x.z), h3 = __float2bfloat16(x.w);
    __nv_bfloat16 l0 = __float2bfloat16(x.x - __bfloat162float(h0));
    __nv_bfloat16 l1 = __float2bfloat16(x.y - __bfloat162float(h1));
    __nv_bfloat16 l2 = __float2bfloat16(x.z - __bfloat162float(h2));
    __nv_bfloat16 l3 = __float2bfloat16(x.w - __bfloat162float(h3));

    __nv_bfloat16* row = g_Wc + (size_t)(v * 4096 + f) * KW;
    __nv_bfloat162* hi = reinterpret_cast<__nv_bfloat162*>(row + q * 4);
    __nv_bfloat162* lo = reinterpret_cast<__nv_bfloat162*>(row + KPAD + q * 4);
    hi[0] = __halves2bfloat162(h0, h1);
    hi[1] = __halves2bfloat162(h2, h3);
    lo[0] = __halves2bfloat162(l0, l1);
    lo[1] = __halves2bfloat162(l2, l3);
}

// ---------------------------------------------------------------------------
// Kernel B: mma.sync bf16 split GEMM.
// C(4096x4096) = A(4096xKPAD) @ B(4096xKPAD)^T per view, 3 bf16 products.
// CTA tile 128x128, BK=32, 8 warps (2M x 4N), 4-stage cp.async pipeline.
// ---------------------------------------------------------------------------
#define PL_A_HI 0
#define PL_A_LO 8192
#define PL_B_HI 16384
#define PL_B_LO 24576
#define STAGE_BYTES 32768
#define NSTAGE 4
#define SMEM_GEMM (NSTAGE * STAGE_BYTES)

__global__ void __launch_bounds__(256, 1) view_gemm_kernel(float* __restrict__ out)
{
    extern __shared__ char smem[];
    const uint32_t sb0 = smem_to_u32(smem);

    const int tid  = threadIdx.x;
    const int lane = tid & 31;
    const int wid  = tid >> 5;
    const int warpM = wid & 1;        // 0..1  (64 rows each)
    const int warpN = wid >> 1;       // 0..3  (32 cols each)

    const int view = blockIdx.z;
    const int m0   = blockIdx.y * 128;
    const int n0   = blockIdx.x * 128;

    const __nv_bfloat16* Abase = g_A  + (size_t)(view * 4096 + m0) * KW;
    const __nv_bfloat16* Bbase = g_Wc + (size_t)(view * 4096 + n0) * KW;

    // Per-thread cp.async assignment: 2 rows x 1 chunk per plane.
    const int lr0 = tid >> 2;          // 0..63
    const int lr1 = lr0 + 64;          // 64..127
    const int lc  = tid & 3;           // 16B chunk 0..3
    const __nv_bfloat16* srcA0 = Abase + (size_t)lr0 * KW + lc * 8;
    const __nv_bfloat16* srcA1 = Abase + (size_t)lr1 * KW + lc * 8;
    const __nv_bfloat16* srcB0 = Bbase + (size_t)lr0 * KW + lc * 8;
    const __nv_bfloat16* srcB1 = Bbase + (size_t)lr1 * KW + lc * 8;
    const uint32_t so0 = swz(lr0, lc);
    const uint32_t so1 = swz(lr1, lc);

    float acc[4][4][4] = {};

    // ---- pipeline prologue: stages 0..2 ----
    #pragma unroll
    for (int s = 0; s < 3; s++) {
        const uint32_t sb = sb0 + s * STAGE_BYTES;
        const size_t kb = (size_t)s * 32;
        cp16(sb + PL_A_HI + so0, srcA0 + kb);
        cp16(sb + PL_A_HI + so1, srcA1 + kb);
        cp16(sb + PL_A_LO + so0, srcA0 + KPAD + kb);
        cp16(sb + PL_A_LO + so1, srcA1 + KPAD + kb);
        cp16(sb + PL_B_HI + so0, srcB0 + kb);
        cp16(sb + PL_B_HI + so1, srcB1 + kb);
        cp16(sb + PL_B_LO + so0, srcB0 + KPAD + kb);
        cp16(sb + PL_B_LO + so1, srcB1 + KPAD + kb);
        CP_COMMIT();
    }

    // ldmatrix lane-dependent address components
    const uint32_t a_r = warpM * 64 + (lane & 15);      // + mi*16
    const uint32_t a_c = (uint32_t)(lane >> 4);         // + ks*2
    const uint32_t b_r = warpN * 32 + (lane >> 4) * 8 + (lane & 7);  // + j*16
    const uint32_t b_c = (uint32_t)((lane >> 3) & 1);   // + ks*2

    for (int ch = 0; ch < NCHUNK; ch++) {
        CP_WAIT2();
        __syncthreads();

        // issue loads for ch+3 (overwrites buffer of ch-1, already consumed)
        if (ch + 3 < NCHUNK) {
            const uint32_t sb = sb0 + ((ch + 3) & 3) * STAGE_BYTES;
            const size_t kb = (size_t)(ch + 3) * 32;
            cp16(sb + PL_A_HI + so0, srcA0 + kb);
            cp16(sb + PL_A_HI + so1, srcA1 + kb);
            cp16(sb + PL_A_LO + so0, srcA0 + KPAD + kb);
            cp16(sb + PL_A_LO + so1, srcA1 + KPAD + kb);
            cp16(sb + PL_B_HI + so0, srcB0 + kb);
            cp16(sb + PL_B_HI + so1, srcB1 + kb);
            cp16(sb + PL_B_LO + so0, srcB0 + KPAD + kb);
            cp16(sb + PL_B_LO + so1, srcB1 + KPAD + kb);
        }
        CP_COMMIT();

        const uint32_t sb = sb0 + (ch & 3) * STAGE_BYTES;

        #pragma unroll
        for (int ks = 0; ks < 2; ks++) {
            uint32_t a_hi[4][4], a_lo[4][4];
            #pragma unroll
            for (int mi = 0; mi < 4; mi++) {
                const uint32_t r = a_r + mi * 16;
                const uint32_t c = a_c + ks * 2;
                const uint32_t off = swz(r, c);
                ldsm4(a_hi[mi], sb + PL_A_HI + off);
                ldsm4(a_lo[mi], sb + PL_A_LO + off);
            }
            uint32_t b_hi[2][4], b_lo[2][4];
            #pragma unroll
            for (int j = 0; j < 2; j++) {
                const uint32_t r = b_r + j * 16;
                const uint32_t c = b_c + ks * 2;
                const uint32_t off = swz(r, c);
                ldsm4(b_hi[j], sb + PL_B_HI + off);
                ldsm4(b_lo[j], sb + PL_B_LO + off);
            }
            #pragma unroll
            for (int mi = 0; mi < 4; mi++) {
                #pragma unroll
                for (int ni = 0; ni < 4; ni++) {
                    const int j = ni >> 1, h = (ni & 1) * 2;
                    const uint32_t bh0 = b_hi[j][h], bh1 = b_hi[j][h + 1];
                    const uint32_t bl0 = b_lo[j][h], bl1 = b_lo[j][h + 1];
                    mma_bf16(acc[mi][ni], a_hi[mi], bh0, bh1);
                    mma_bf16(acc[mi][ni], a_hi[mi], bl0, bl1);
                    mma_bf16(acc[mi][ni], a_lo[mi], bh0, bh1);
                }
            }
        }
    }

    // ---- epilogue: direct float2 stores ----
    float* C = out + (size_t)(1 + view) * EMB_ELEMS;
    const int rbase = m0 + warpM * 64 + (lane >> 2);
    const int cbase = n0 + warpN * 32 + (lane & 3) * 2;
    #pragma unroll
    for (int mi = 0; mi < 4; mi++) {
        #pragma unroll
        for (int ni = 0; ni < 4; ni++) {
            const size_t r0 = (size_t)(rbase + mi * 16);
            const int cc = cbase + ni * 8;
            *reinterpret_cast<float2*>(&C[r0 * FDIM + cc]) =
                make_float2(acc[mi][ni][0], acc[mi][ni][1]);
            *reinterpret_cast<float2*>(&C[(r0 + 8) * FDIM + cc]) =
                make_float2(acc[mi][ni][2], acc[mi][ni][3]);
        }
    }
}

// ---------------------------------------------------------------------------
// Host launch
// Inputs: feature_emb, kp_W, W_triu, W_tril (all fp32)
// Output: [embs_flatten | view_1 | view_2], each 4096*4096 fp32.
// ---------------------------------------------------------------------------
extern "C" void kernel_launch(void* const* d_in, const int* in_sizes, int n_in,
                              void* d_out, int out_size)
{
    const float* femb   = (const float*)d_in[0];
    const float* kpW    = (const float*)d_in[1];
    const float* W_triu = (const float*)d_in[2];
    const float* W_tril = (const float*)d_in[3];
    float* out = (float*)d_out;

    // Segment 0: embs_flatten is feature_emb flattened
    cudaMemcpyAsync(out, femb, (size_t)EMB_ELEMS * sizeof(float),
                    cudaMemcpyDeviceToDevice, 0);

    // Build bf16 hi/lo operand planes
    const int convThreads = 256;
    const int convBlocks  = (int)(((size_t)2 * 4096 * 520 + convThreads - 1) / convThreads);
    convert_w_kernel<<<convBlocks, convThreads>>>(W_triu, W_tril);
    kp_pair_kernel<<<BATCH, 256>>>(femb, kpW);

    // Big GEMMs on mma.sync tensor cores
    cudaFuncSetAttribute(view_gemm_kernel,
                         cudaFuncAttributeMaxDynamicSharedMemorySize, SMEM_GEMM);
    dim3 grid(FDIM / 128, BATCH / 128, 2);
    view_gemm_kernel<<<grid, 256, SMEM_GEMM>>>(out);
}

// round 4
// speedup vs baseline: 3.7887x; 1.4260x over previous
#include <cuda_runtime.h>
#include <cuda_fp16.h>
#include <cstdint>

// ---------------------------------------------------------------------------
// Problem constants
// ---------------------------------------------------------------------------
#define BATCH 4096
#define NDIM  64
#define FDIM  4096
#define KP    2080          // N*(N+1)/2
#define KPAD  2112          // KP padded to a multiple of 32 (66 chunks of 32)
#define KW    (2*KPAD)      // row width of A hi|lo planes (4224 fp16)
#define EMB_ELEMS (4096u*4096u)
#define NCHUNK (KPAD/32)    // 66

// A planes (gathered triu/tril, fp16 hi + lo residual). Rows [0,4096) = view0,
// [4096,8192) = view1. Cols [0,KPAD) = hi, [KPAD,2*KPAD) = lo.
// B plane (W_triu/W_tril, single fp16). Pad cols stay zero (.bss zero-init).
__device__ __align__(1024) __half g_A [(size_t)8192 * KW];
__device__ __align__(1024) __half g_Wc[(size_t)8192 * KPAD];

// ---------------------------------------------------------------------------
// Small helpers
// ---------------------------------------------------------------------------
__device__ __forceinline__ uint32_t smem_to_u32(const void* p) {
    uint32_t a;
    asm("{ .reg .u64 t; cvta.to.shared.u64 t, %1; cvt.u32.u64 %0, t; }"
        : "=r"(a) : "l"(p));
    return a;
}

__device__ __forceinline__ void cp16(uint32_t dst, const void* src) {
    asm volatile("cp.async.cg.shared.global [%0], [%1], 16;"
                 :: "r"(dst), "l"(src));
}
#define CP_COMMIT() asm volatile("cp.async.commit_group;" ::: "memory")
#define CP_WAIT2()  asm volatile("cp.async.wait_group 2;" ::: "memory")

__device__ __forceinline__ void ldsm4(uint32_t (&r)[4], uint32_t addr) {
    asm volatile("ldmatrix.sync.aligned.m8n8.x4.shared.b16 {%0,%1,%2,%3}, [%4];"
                 : "=r"(r[0]), "=r"(r[1]), "=r"(r[2]), "=r"(r[3]) : "r"(addr));
}

__device__ __forceinline__ void mma_fp16(float (&d)[4], const uint32_t (&a)[4],
                                         uint32_t b0, uint32_t b1) {
    asm volatile(
        "mma.sync.aligned.m16n8k16.row.col.f32.f16.f16.f32 "
        "{%0,%1,%2,%3}, {%4,%5,%6,%7}, {%8,%9}, {%0,%1,%2,%3};"
        : "+f"(d[0]), "+f"(d[1]), "+f"(d[2]), "+f"(d[3])
        : "r"(a[0]), "r"(a[1]), "r"(a[2]), "r"(a[3]), "r"(b0), "r"(b1));
}

// XOR swizzle: tile row r, 16B-chunk c (0..3) -> byte offset within a plane.
// Conflict-free for ldmatrix 8-row phases and cp.async store waves.
__device__ __forceinline__ uint32_t swz(uint32_t r, uint32_t c) {
    return (r * 4u + (c ^ ((r >> 1) & 3u))) * 16u;
}

// ---------------------------------------------------------------------------
// Kernel A: per-batch embs_kp = F @ kpW @ F^T, scatter triu/tril as fp16 hi/lo
// ---------------------------------------------------------------------------
__device__ __forceinline__ void split_store(__half* row, int p, float v) {
    __half h = __float2half_rn(v);
    float lo = v - __half2float(h);
    row[p]        = h;
    row[KPAD + p] = __float2half_rn(lo);
}

__global__ __launch_bounds__(256) void kp_pair_kernel(
    const float* __restrict__ femb, const float* __restrict__ kpW)
{
    __shared__ float Fs[64 * 65];
    __shared__ float WT[64 * 64];

    const int b   = blockIdx.x;
    const int tid = threadIdx.x;
    const float* Fb = femb + (size_t)b * (NDIM * NDIM);

    for (int i = tid; i < 1024; i += 256) {
        float4 v = ((const float4*)Fb)[i];
        int row = i >> 4, col = (i & 15) << 2;
        float* dst = &Fs[row * 65 + col];
        dst[0] = v.x; dst[1] = v.y; dst[2] = v.z; dst[3] = v.w;
    }
    for (int i = tid; i < 1024; i += 256)
        ((float4*)WT)[i] = ((const float4*)kpW)[i];
    __syncthreads();

    const int ty = tid >> 4, tx = tid & 15;
    const int r0 = ty * 4, c0 = tx * 4;

    float t[4][4] = {};
    #pragma unroll 8
    for (int d = 0; d < 64; d++) {
        float a0 = Fs[(r0 + 0) * 65 + d];
        float a1 = Fs[(r0 + 1) * 65 + d];
        float a2 = Fs[(r0 + 2) * 65 + d];
        float a3 = Fs[(r0 + 3) * 65 + d];
        float4 bb = *(const float4*)&WT[d * 64 + c0];
        t[0][0] += a0 * bb.x; t[0][1] += a0 * bb.y; t[0][2] += a0 * bb.z; t[0][3] += a0 * bb.w;
        t[1][0] += a1 * bb.x; t[1][1] += a1 * bb.y; t[1][2] += a1 * bb.z; t[1][3] += a1 * bb.w;
        t[2][0] += a2 * bb.x; t[2][1] += a2 * bb.y; t[2][2] += a2 * bb.z; t[2][3] += a2 * bb.w;
        t[3][0] += a3 * bb.x; t[3][1] += a3 * bb.y; t[3][2] += a3 * bb.z; t[3][3] += a3 * bb.w;
    }
    __syncthreads();
    #pragma unroll
    for (int i = 0; i < 4; i++)
        *(float4*)&WT[(r0 + i) * 64 + c0] = make_float4(t[i][0], t[i][1], t[i][2], t[i][3]);
    __syncthreads();

    float e[4][4] = {};
    #pragma unroll 8
    for (int d = 0; d < 64; d++) {
        float a0 = WT[(r0 + 0) * 64 + d];
        float a1 = WT[(r0 + 1) * 64 + d];
        float a2 = WT[(r0 + 2) * 64 + d];
        float a3 = WT[(r0 + 3) * 64 + d];
        float b0 = Fs[(c0 + 0) * 65 + d];
        float b1 = Fs[(c0 + 1) * 65 + d];
        float b2 = Fs[(c0 + 2) * 65 + d];
        float b3 = Fs[(c0 + 3) * 65 + d];
        e[0][0] += a0 * b0; e[0][1] += a0 * b1; e[0][2] += a0 * b2; e[0][3] += a0 * b3;
        e[1][0] += a1 * b0; e[1][1] += a1 * b1; e[1][2] += a1 * b2; e[1][3] += a1 * b3;
        e[2][0] += a2 * b0; e[2][1] += a2 * b1; e[2][2] += a2 * b2; e[2][3] += a2 * b3;
        e[3][0] += a3 * b0; e[3][1] += a3 * b1; e[3][2] += a3 * b2; e[3][3] += a3 * b3;
    }

    __half* tri_row = g_A + (size_t)b * KW;            // view 0
    __half* trl_row = g_A + (size_t)(4096 + b) * KW;   // view 1
    #pragma unroll
    for (int i = 0; i < 4; i++) {
        int r = r0 + i;
        int tri_base = r * 64 - (r * (r - 1)) / 2 - r;
        int trl_base = (r * (r + 1)) / 2;
        #pragma unroll
        for (int j = 0; j < 4; j++) {
            int c = c0 + j;
            float v = e[i][j];
            if (r <= c) split_store(tri_row, tri_base + c, v);
            if (r >= c) split_store(trl_row, trl_base + c, v);
        }
    }
}

// ---------------------------------------------------------------------------
// Kernel W: convert W_triu/W_tril fp32 -> single fp16 plane in g_Wc
// ---------------------------------------------------------------------------
__global__ __launch_bounds__(256) void convert_w_kernel(
    const float* __restrict__ Wt, const float* __restrict__ Wl)
{
    const size_t total = (size_t)2 * 4096 * 520;   // float4 quads
    size_t idx = (size_t)blockIdx.x * blockDim.x + threadIdx.x;
    if (idx >= total) return;
    int v = (int)(idx / ((size_t)4096 * 520));
    size_t rem = idx - (size_t)v * 4096 * 520;
    int f = (int)(rem / 520), q = (int)(rem % 520);

    const float* W = v ? Wl : Wt;
    float4 x = reinterpret_cast<const float4*>(W + (size_t)f * KP)[q];

    __half* row = g_Wc + (size_t)(v * 4096 + f) * KPAD;
    __half2* o = reinterpret_cast<__half2*>(row + q * 4);
    o[0] = __floats2half2_rn(x.x, x.y);
    o[1] = __floats2half2_rn(x.z, x.w);
}

// ---------------------------------------------------------------------------
// Kernel B: mma.sync fp16 2-product split GEMM.
// C(4096x4096) = A(4096xKPAD) @ B(4096xKPAD)^T per view,
// C = A_hi@B + A_lo@B (fp32 accumulate).
// CTA tile 128(M) x 256(N), BK=32, 8 warps (2M x 4N, warp tile 64x64),
// 4-stage cp.async pipeline.
// ---------------------------------------------------------------------------
#define PL_A_HI 0
#define PL_A_LO 8192
#define PL_B    16384       // 16KB plane (256 rows)
#define STAGE_BYTES 32768
#define NSTAGE 4
#define SMEM_GEMM (NSTAGE * STAGE_BYTES)

__global__ void __launch_bounds__(256, 1) view_gemm_kernel(float* __restrict__ out)
{
    extern __shared__ char smem[];
    const uint32_t sb0 = smem_to_u32(smem);

    const int tid  = threadIdx.x;
    const int lane = tid & 31;
    const int wid  = tid >> 5;
    const int warpM = wid & 1;        // 0..1  (64 rows each)
    const int warpN = wid >> 1;       // 0..3  (64 cols each)

    const int view = blockIdx.z;
    const int m0   = blockIdx.y * 128;
    const int n0   = blockIdx.x * 256;

    const __half* Abase = g_A  + (size_t)(view * 4096 + m0) * KW;
    const __half* Bbase = g_Wc + (size_t)(view * 4096 + n0) * KPAD;

    // cp.async assignment: 8 x 16B per thread per stage.
    const int lr0 = tid >> 2;          // 0..63
    const int lc  = tid & 3;           // 16B chunk 0..3
    const __half* srcA0 = Abase + (size_t)lr0 * KW + lc * 8;
    const __half* srcA1 = Abase + (size_t)(lr0 + 64) * KW + lc * 8;
    const __half* srcB0 = Bbase + (size_t)lr0 * KPAD + lc * 8;          // rows 0..63
    const uint32_t soA0 = swz(lr0, lc);
    const uint32_t soA1 = swz(lr0 + 64, lc);

    float acc[4][8][4] = {};

    // ---- pipeline prologue: stages 0..2 ----
    #pragma unroll
    for (int s = 0; s < 3; s++) {
        const uint32_t sb = sb0 + s * STAGE_BYTES;
        const size_t kb = (size_t)s * 32;
        cp16(sb + PL_A_HI + soA0, srcA0 + kb);
        cp16(sb + PL_A_HI + soA1, srcA1 + kb);
        cp16(sb + PL_A_LO + soA0, srcA0 + KPAD + kb);
        cp16(sb + PL_A_LO + soA1, srcA1 + KPAD + kb);
        #pragma unroll
        for (int g = 0; g < 4; g++)
            cp16(sb + PL_B + swz(lr0 + g * 64, lc),
                 srcB0 + (size_t)(g * 64) * KPAD + kb);
        CP_COMMIT();
    }

    // ldmatrix lane-dependent address components
    const uint32_t a_r = warpM * 64 + (lane & 15);                   // + mi*16
    const uint32_t a_c = (uint32_t)(lane >> 4);                      // + ks*2
    const uint32_t b_r = warpN * 64 + (lane >> 4) * 8 + (lane & 7);  // + j*16
    const uint32_t b_c = (uint32_t)((lane >> 3) & 1);                // + ks*2

    for (int ch = 0; ch < NCHUNK; ch++) {
        CP_WAIT2();
        __syncthreads();

        // issue loads for ch+3 (overwrites buffer of ch-1, already consumed)
        if (ch + 3 < NCHUNK) {
            const uint32_t sb = sb0 + ((ch + 3) & 3) * STAGE_BYTES;
            const size_t kb = (size_t)(ch + 3) * 32;
            cp16(sb + PL_A_HI + soA0, srcA0 + kb);
            cp16(sb + PL_A_HI + soA1, srcA1 + kb);
            cp16(sb + PL_A_LO + soA0, srcA0 + KPAD + kb);
            cp16(sb + PL_A_LO + soA1, srcA1 + KPAD + kb);
            #pragma unroll
            for (int g = 0; g < 4; g++)
                cp16(sb + PL_B + swz(lr0 + g * 64, lc),
                     srcB0 + (size_t)(g * 64) * KPAD + kb);
        }
        CP_COMMIT();

        const uint32_t sb = sb0 + (ch & 3) * STAGE_BYTES;

        #pragma unroll
        for (int ks = 0; ks < 2; ks++) {
            uint32_t b_f[4][4];
            #pragma unroll
            for (int j = 0; j < 4; j++) {
                const uint32_t off = swz(b_r + j * 16, b_c + ks * 2);
                ldsm4(b_f[j], sb + PL_B + off);
            }
            uint32_t a_hi[4][4], a_lo[4][4];
            #pragma unroll
            for (int mi = 0; mi < 4; mi++) {
                const uint32_t off = swz(a_r + mi * 16, a_c + ks * 2);
                ldsm4(a_hi[mi], sb + PL_A_HI + off);
                ldsm4(a_lo[mi], sb + PL_A_LO + off);
            }
            #pragma unroll
            for (int mi = 0; mi < 4; mi++) {
                #pragma unroll
                for (int ni = 0; ni < 8; ni++) {
                    const int j = ni >> 1, h = (ni & 1) * 2;
                    const uint32_t b0 = b_f[j][h], b1 = b_f[j][h + 1];
                    mma_fp16(acc[mi][ni], a_hi[mi], b0, b1);
                    mma_fp16(acc[mi][ni], a_lo[mi], b0, b1);
                }
            }
        }
    }

    // ---- epilogue: direct float2 stores ----
    float* C = out + (size_t)(1 + view) * EMB_ELEMS;
    const int rbase = m0 + warpM * 64 + (lane >> 2);
    const int cbase = n0 + warpN * 64 + (lane & 3) * 2;
    #pragma unroll
    for (int mi = 0; mi < 4; mi++) {
        #pragma unroll
        for (int ni = 0; ni < 8; ni++) {
            const size_t r0 = (size_t)(rbase + mi * 16);
            const int cc = cbase + ni * 8;
            *reinterpret_cast<float2*>(&C[r0 * FDIM + cc]) =
                make_float2(acc[mi][ni][0], acc[mi][ni][1]);
            *reinterpret_cast<float2*>(&C[(r0 + 8) * FDIM + cc]) =
                make_float2(acc[mi][ni][2], acc[mi][ni][3]);
        }
    }
}

// ---------------------------------------------------------------------------
// Host launch
// Inputs: feature_emb, kp_W, W_triu, W_tril (all fp32)
// Output: [embs_flatten | view_1 | view_2], each 4096*4096 fp32.
// ---------------------------------------------------------------------------
extern "C" void kernel_launch(void* const* d_in, const int* in_sizes, int n_in,
                              void* d_out, int out_size)
{
    const float* femb   = (const float*)d_in[0];
    const float* kpW    = (const float*)d_in[1];
    const float* W_triu = (const float*)d_in[2];
    const float* W_tril = (const float*)d_in[3];
    float* out = (float*)d_out;

    // Segment 0: embs_flatten is feature_emb flattened
    cudaMemcpyAsync(out, femb, (size_t)EMB_ELEMS * sizeof(float),
                    cudaMemcpyDeviceToDevice, 0);

    // Build fp16 operand planes
    const int convThreads = 256;
    const int convBlocks  = (int)(((size_t)2 * 4096 * 520 + convThreads - 1) / convThreads);
    convert_w_kernel<<<convBlocks, convThreads>>>(W_triu, W_tril);
    kp_pair_kernel<<<BATCH, 256>>>(femb, kpW);

    // Big GEMMs on mma.sync tensor cores
    cudaFuncSetAttribute(view_gemm_kernel,
                         cudaFuncAttributeMaxDynamicSharedMemorySize, SMEM_GEMM);
    dim3 grid(FDIM / 256, BATCH / 128, 2);
    view_gemm_kernel<<<grid, 256, SMEM_GEMM>>>(out);
}

// round 5
// speedup vs baseline: 5.8317x; 1.5392x over previous
#include <cuda_runtime.h>
#include <cuda_fp16.h>
#include <cstdint>

// ---------------------------------------------------------------------------
// Problem constants
// ---------------------------------------------------------------------------
#define BATCH 4096
#define NDIM  64
#define FDIM  4096
#define KP    2080          // N*(N+1)/2
#define KPAD  2112          // KP padded to a multiple of 32 (66 chunks of 32)
#define EMB_ELEMS (4096u*4096u)
#define NCHUNK (KPAD/32)    // 66

// fp16 operand planes. Rows [0,4096) = view0 (triu / W_triu), [4096,8192) = view1.
// Pad cols [2080,2112) stay zero (.bss zero-init, never written).
__device__ __align__(1024) __half g_A [(size_t)8192 * KPAD];
__device__ __align__(1024) __half g_Wc[(size_t)8192 * KPAD];

// ---------------------------------------------------------------------------
// Small helpers
// ---------------------------------------------------------------------------
__device__ __forceinline__ uint32_t smem_to_u32(const void* p) {
    uint32_t a;
    asm("{ .reg .u64 t; cvta.to.shared.u64 t, %1; cvt.u32.u64 %0, t; }"
        : "=r"(a) : "l"(p));
    return a;
}

__device__ __forceinline__ void cp16(uint32_t dst, const void* src) {
    asm volatile("cp.async.cg.shared.global [%0], [%1], 16;"
                 :: "r"(dst), "l"(src));
}
#define CP_COMMIT() asm volatile("cp.async.commit_group;" ::: "memory")
#define CP_WAIT3()  asm volatile("cp.async.wait_group 3;" ::: "memory")

__device__ __forceinline__ void ldsm4(uint32_t (&r)[4], uint32_t addr) {
    asm volatile("ldmatrix.sync.aligned.m8n8.x4.shared.b16 {%0,%1,%2,%3}, [%4];"
                 : "=r"(r[0]), "=r"(r[1]), "=r"(r[2]), "=r"(r[3]) : "r"(addr));
}

__device__ __forceinline__ void mma_fp16(float (&d)[4], const uint32_t (&a)[4],
                                         uint32_t b0, uint32_t b1) {
    asm volatile(
        "mma.sync.aligned.m16n8k16.row.col.f32.f16.f16.f32 "
        "{%0,%1,%2,%3}, {%4,%5,%6,%7}, {%8,%9}, {%0,%1,%2,%3};"
        : "+f"(d[0]), "+f"(d[1]), "+f"(d[2]), "+f"(d[3])
        : "r"(a[0]), "r"(a[1]), "r"(a[2]), "r"(a[3]), "r"(b0), "r"(b1));
}

// XOR swizzle: tile row r, 16B-chunk c (0..3) -> byte offset within a plane
// (rows are 32 fp16 = 64B = 4 chunks). Conflict-free for ldmatrix 8-row
// phases and cp.async store waves.
__device__ __forceinline__ uint32_t swz(uint32_t r, uint32_t c) {
    return (r * 4u + (c ^ ((r >> 1) & 3u))) * 16u;
}

// ---------------------------------------------------------------------------
// Kernel A: per-batch embs_kp = F @ kpW @ F^T, scatter triu/tril as fp16
// ---------------------------------------------------------------------------
__global__ __launch_bounds__(256) void kp_pair_kernel(
    const float* __restrict__ femb, const float* __restrict__ kpW)
{
    __shared__ float Fs[64 * 65];
    __shared__ float WT[64 * 64];

    const int b   = blockIdx.x;
    const int tid = threadIdx.x;
    const float* Fb = femb + (size_t)b * (NDIM * NDIM);

    for (int i = tid; i < 1024; i += 256) {
        float4 v = ((const float4*)Fb)[i];
        int row = i >> 4, col = (i & 15) << 2;
        float* dst = &Fs[row * 65 + col];
        dst[0] = v.x; dst[1] = v.y; dst[2] = v.z; dst[3] = v.w;
    }
    for (int i = tid; i < 1024; i += 256)
        ((float4*)WT)[i] = ((const float4*)kpW)[i];
    __syncthreads();

    const int ty = tid >> 4, tx = tid & 15;
    const int r0 = ty * 4, c0 = tx * 4;

    float t[4][4] = {};
    #pragma unroll 8
    for (int d = 0; d < 64; d++) {
        float a0 = Fs[(r0 + 0) * 65 + d];
        float a1 = Fs[(r0 + 1) * 65 + d];
        float a2 = Fs[(r0 + 2) * 65 + d];
        float a3 = Fs[(r0 + 3) * 65 + d];
        float4 bb = *(const float4*)&WT[d * 64 + c0];
        t[0][0] += a0 * bb.x; t[0][1] += a0 * bb.y; t[0][2] += a0 * bb.z; t[0][3] += a0 * bb.w;
        t[1][0] += a1 * bb.x; t[1][1] += a1 * bb.y; t[1][2] += a1 * bb.z; t[1][3] += a1 * bb.w;
        t[2][0] += a2 * bb.x; t[2][1] += a2 * bb.y; t[2][2] += a2 * bb.z; t[2][3] += a2 * bb.w;
        t[3][0] += a3 * bb.x; t[3][1] += a3 * bb.y; t[3][2] += a3 * bb.z; t[3][3] += a3 * bb.w;
    }
    __syncthreads();
    #pragma unroll
    for (int i = 0; i < 4; i++)
        *(float4*)&WT[(r0 + i) * 64 + c0] = make_float4(t[i][0], t[i][1], t[i][2], t[i][3]);
    __syncthreads();

    float e[4][4] = {};
    #pragma unroll 8
    for (int d = 0; d < 64; d++) {
        float a0 = WT[(r0 + 0) * 64 + d];
        float a1 = WT[(r0 + 1) * 64 + d];
        float a2 = WT[(r0 + 2) * 64 + d];
        float a3 = WT[(r0 + 3) * 64 + d];
        float b0 = Fs[(c0 + 0) * 65 + d];
        float b1 = Fs[(c0 + 1) * 65 + d];
        float b2 = Fs[(c0 + 2) * 65 + d];
        float b3 = Fs[(c0 + 3) * 65 + d];
        e[0][0] += a0 * b0; e[0][1] += a0 * b1; e[0][2] += a0 * b2; e[0][3] += a0 * b3;
        e[1][0] += a1 * b0; e[1][1] += a1 * b1; e[1][2] += a1 * b2; e[1][3] += a1 * b3;
        e[2][0] += a2 * b0; e[2][1] += a2 * b1; e[2][2] += a2 * b2; e[2][3] += a2 * b3;
        e[3][0] += a3 * b0; e[3][1] += a3 * b1; e[3][2] += a3 * b2; e[3][3] += a3 * b3;
    }

    __half* tri_row = g_A + (size_t)b * KPAD;            // view 0
    __half* trl_row = g_A + (size_t)(4096 + b) * KPAD;   // view 1
    #pragma unroll
    for (int i = 0; i < 4; i++) {
        int r = r0 + i;
        int tri_base = r * 64 - (r * (r - 1)) / 2 - r;
        int trl_base = (r * (r + 1)) / 2;
        #pragma unroll
        for (int j = 0; j < 4; j++) {
            int c = c0 + j;
            __half v = __float2half_rn(e[i][j]);
            if (r <= c) tri_row[tri_base + c] = v;
            if (r >= c) trl_row[trl_base + c] = v;
        }
    }
}

// ---------------------------------------------------------------------------
// Kernel W: convert W_triu/W_tril fp32 -> fp16 plane in g_Wc
// ---------------------------------------------------------------------------
__global__ __launch_bounds__(256) void convert_w_kernel(
    const float* __restrict__ Wt, const float* __restrict__ Wl)
{
    const size_t total = (size_t)2 * 4096 * 520;   // float4 quads
    size_t idx = (size_t)blockIdx.x * blockDim.x + threadIdx.x;
    if (idx >= total) return;
    int v = (int)(idx / ((size_t)4096 * 520));
    size_t rem = idx - (size_t)v * 4096 * 520;
    int f = (int)(rem / 520), q = (int)(rem % 520);

    const float* W = v ? Wl : Wt;
    float4 x = reinterpret_cast<const float4*>(W + (size_t)f * KP)[q];

    __half* row = g_Wc + (size_t)(v * 4096 + f) * KPAD;
    __half2* o = reinterpret_cast<__half2*>(row + q * 4);
    o[0] = __floats2half2_rn(x.x, x.y);
    o[1] = __floats2half2_rn(x.z, x.w);
}

// ---------------------------------------------------------------------------
// Kernel B: mma.sync fp16 GEMM (single product, fp32 accumulate).
// C(4096x4096) = A(4096xKPAD) @ B(4096xKPAD)^T per view.
// CTA tile 128(M) x 256(N), BK=32, 8 warps (2M x 4N, warp tile 64x64),
// 5-stage cp.async pipeline.
// ---------------------------------------------------------------------------
#define PL_A 0
#define PL_B 8192           // A plane 8KB, B plane 16KB
#define STAGE_BYTES 24576
#define NSTAGE 5
#define SMEM_GEMM (NSTAGE * STAGE_BYTES)

__global__ void __launch_bounds__(256, 1) view_gemm_kernel(float* __restrict__ out)
{
    extern __shared__ char smem[];
    const uint32_t sb0 = smem_to_u32(smem);

    const int tid  = threadIdx.x;
    const int lane = tid & 31;
    const int wid  = tid >> 5;
    const int warpM = wid & 1;        // 0..1  (64 rows each)
    const int warpN = wid >> 1;       // 0..3  (64 cols each)

    const int view = blockIdx.z;
    const int m0   = blockIdx.y * 128;
    const int n0   = blockIdx.x * 256;

    const __half* Abase = g_A  + (size_t)(view * 4096 + m0) * KPAD;
    const __half* Bbase = g_Wc + (size_t)(view * 4096 + n0) * KPAD;

    // cp.async assignment: 6 x 16B per thread per stage (2 A rows + 4 B rows).
    const int lr0 = tid >> 2;          // 0..63
    const int lc  = tid & 3;           // 16B chunk 0..3
    const __half* srcA0 = Abase + (size_t)lr0 * KPAD + lc * 8;
    const __half* srcA1 = Abase + (size_t)(lr0 + 64) * KPAD + lc * 8;
    const __half* srcB0 = Bbase + (size_t)lr0 * KPAD + lc * 8;
    const uint32_t soA0 = swz(lr0, lc);
    const uint32_t soA1 = swz(lr0 + 64, lc);

    float acc[4][8][4] = {};

    // ---- pipeline prologue: stages 0..3 ----
    #pragma unroll
    for (int s = 0; s < 4; s++) {
        const uint32_t sb = sb0 + s * STAGE_BYTES;
        const size_t kb = (size_t)s * 32;
        cp16(sb + PL_A + soA0, srcA0 + kb);
        cp16(sb + PL_A + soA1, srcA1 + kb);
        #pragma unroll
        for (int g = 0; g < 4; g++)
            cp16(sb + PL_B + swz(lr0 + g * 64, lc),
                 srcB0 + (size_t)(g * 64) * KPAD + kb);
        CP_COMMIT();
    }

    // ldmatrix lane-dependent address components
    const uint32_t a_r = warpM * 64 + (lane & 15);                   // + mi*16
    const uint32_t a_c = (uint32_t)(lane >> 4);                      // + ks*2
    const uint32_t b_r = warpN * 64 + (lane >> 4) * 8 + (lane & 7);  // + j*16
    const uint32_t b_c = (uint32_t)((lane >> 3) & 1);                // + ks*2

    int stage_c = 0;   // compute stage index (mod NSTAGE)
    int stage_l = 4;   // load stage index (mod NSTAGE)

    for (int ch = 0; ch < NCHUNK; ch++) {
        CP_WAIT3();
        __syncthreads();

        // issue loads for ch+4 (overwrites buffer of ch-1, already consumed)
        if (ch + 4 < NCHUNK) {
            const uint32_t sb = sb0 + stage_l * STAGE_BYTES;
            const size_t kb = (size_t)(ch + 4) * 32;
            cp16(sb + PL_A + soA0, srcA0 + kb);
            cp16(sb + PL_A + soA1, srcA1 + kb);
            #pragma unroll
            for (int g = 0; g < 4; g++)
                cp16(sb + PL_B + swz(lr0 + g * 64, lc),
                     srcB0 + (size_t)(g * 64) * KPAD + kb);
        }
        CP_COMMIT();
        if (++stage_l == NSTAGE) stage_l = 0;

        const uint32_t sb = sb0 + stage_c * STAGE_BYTES;
        if (++stage_c == NSTAGE) stage_c = 0;

        #pragma unroll
        for (int ks = 0; ks < 2; ks++) {
            uint32_t b_f[4][4];
            #pragma unroll
            for (int j = 0; j < 4; j++) {
                const uint32_t off = swz(b_r + j * 16, b_c + ks * 2);
                ldsm4(b_f[j], sb + PL_B + off);
            }
            uint32_t a_f[4][4];
            #pragma unroll
            for (int mi = 0; mi < 4; mi++) {
                const uint32_t off = swz(a_r + mi * 16, a_c + ks * 2);
                ldsm4(a_f[mi], sb + PL_A + off);
            }
            #pragma unroll
            for (int mi = 0; mi < 4; mi++) {
                #pragma unroll
                for (int ni = 0; ni < 8; ni++) {
                    const int j = ni >> 1, h = (ni & 1) * 2;
                    mma_fp16(acc[mi][ni], a_f[mi], b_f[j][h], b_f[j][h + 1]);
                }
            }
        }
    }

    // ---- epilogue: direct float2 stores ----
    float* C = out + (size_t)(1 + view) * EMB_ELEMS;
    const int rbase = m0 + warpM * 64 + (lane >> 2);
    const int cbase = n0 + warpN * 64 + (lane & 3) * 2;
    #pragma unroll
    for (int mi = 0; mi < 4; mi++) {
        #pragma unroll
        for (int ni = 0; ni < 8; ni++) {
            const size_t r0 = (size_t)(rbase + mi * 16);
            const int cc = cbase + ni * 8;
            *reinterpret_cast<float2*>(&C[r0 * FDIM + cc]) =
                make_float2(acc[mi][ni][0], acc[mi][ni][1]);
            *reinterpret_cast<float2*>(&C[(r0 + 8) * FDIM + cc]) =
                make_float2(acc[mi][ni][2], acc[mi][ni][3]);
        }
    }
}

// ---------------------------------------------------------------------------
// Host launch
// Inputs: feature_emb, kp_W, W_triu, W_tril (all fp32)
// Output: [embs_flatten | view_1 | view_2], each 4096*4096 fp32.
// ---------------------------------------------------------------------------
extern "C" void kernel_launch(void* const* d_in, const int* in_sizes, int n_in,
                              void* d_out, int out_size)
{
    const float* femb   = (const float*)d_in[0];
    const float* kpW    = (const float*)d_in[1];
    const float* W_triu = (const float*)d_in[2];
    const float* W_tril = (const float*)d_in[3];
    float* out = (float*)d_out;

    // Segment 0: embs_flatten is feature_emb flattened
    cudaMemcpyAsync(out, femb, (size_t)EMB_ELEMS * sizeof(float),
                    cudaMemcpyDeviceToDevice, 0);

    // Build fp16 operand planes
    const int convThreads = 256;
    const int convBlocks  = (int)(((size_t)2 * 4096 * 520 + convThreads - 1) / convThreads);
    convert_w_kernel<<<convBlocks, convThreads>>>(W_triu, W_tril);
    kp_pair_kernel<<<BATCH, 256>>>(femb, kpW);

    // Big GEMMs on mma.sync tensor cores
    cudaFuncSetAttribute(view_gemm_kernel,
                         cudaFuncAttributeMaxDynamicSharedMemorySize, SMEM_GEMM);
    dim3 grid(FDIM / 256, BATCH / 128, 2);
    view_gemm_kernel<<<grid, 256, SMEM_GEMM>>>(out);
}